// round 3
// baseline (speedup 1.0000x reference)
#include <cuda_runtime.h>
#include <cstdint>

// Patcher: x (8,3,1024,1024) fp32, patch=24, stride=16, reflect pad m=4.
// out[((b*64+ph)*64+pw)*1728 + (i*24+j)*3 + c] = x[b,c, ry, rx]
//   ry = reflect(ph*16+i-4), rx = reflect(pw*16+j-4), reflect: q<0->-q; q>1023->2046-q.
//
// Block = (b, ph, pg): 8 consecutive patches (pw = 8*pg .. 8*pg+7).
//  Phase 1: stage input tile [3ch][24 rows][152 cols] in smem, coalesced LDG,
//           per-element reflect (uniform edge handling).
//  Phase 2: each thread writes consecutive float4s of the block's contiguous
//           13824-float output region, gathering 4 scalars from smem.

static constexpr unsigned HWu = 1024u * 1024u;
static constexpr long long TOTAL_ELEMS = 56623104LL;
static constexpr unsigned TILE_LOADS = 3u * 24u * 152u;   // 10944 floats
static constexpr unsigned TILE_OUT4  = 8u * 432u;         // 3456 float4 per block
static constexpr unsigned RSd = 153u;                     // smem row stride (floats)
static constexpr unsigned CSd = 3673u;                    // smem channel stride
static constexpr unsigned SMEM_FLOATS = 2u*CSd + 23u*RSd + 152u; // 11017

__device__ __forceinline__ int reflect_idx(int q) {
    q = (q < 0) ? -q : q;
    q = (q > 1023) ? (2046 - q) : q;
    return q;
}

__global__ void __launch_bounds__(256)
patcher_kernel(const float* __restrict__ x, float* __restrict__ out,
               unsigned out_size) {
    __shared__ float s[SMEM_FLOATS];

    unsigned bid = blockIdx.x;
    unsigned tid = threadIdx.x;
    unsigned pg = bid & 7u;          // pw0 = 8*pg
    unsigned ph = (bid >> 3) & 63u;
    unsigned b  = bid >> 9;          // 0..7
    unsigned pw0 = pg << 3;

    // Fused tail fill (flattened (nH,nW) = (64,64) appended after patches).
    if (bid == 0 && tid < 32u) {
        unsigned idx = (unsigned)TOTAL_ELEMS + tid;
        if (idx < out_size) out[idx] = 64.0f;
    }

    // ---- Phase 1: stage tile ----
    const float* xb = x + (size_t)b * (3u * HWu);
    int ybase = (int)(ph * 16u) - 4;
    int xbase = (int)(pw0 * 16u) - 4;

    #pragma unroll 4
    for (unsigned idx = tid; idx < TILE_LOADS; idx += 256u) {
        unsigned xl   = idx % 152u;
        unsigned rest = idx / 152u;
        unsigned r = rest % 24u;
        unsigned c = rest / 24u;
        int ry = reflect_idx(ybase + (int)r);
        int rx = reflect_idx(xbase + (int)xl);
        s[c * CSd + r * RSd + xl] =
            __ldg(xb + (size_t)c * HWu + (unsigned)ry * 1024u + (unsigned)rx);
    }
    __syncthreads();

    // ---- Phase 2: contiguous float4 stores ----
    unsigned patch0 = (b << 12) + (ph << 6) + pw0;
    float4* o4 = reinterpret_cast<float4*>(out) + (size_t)patch0 * 432u;

    #pragma unroll 4
    for (unsigned idx = tid; idx < TILE_OUT4; idx += 256u) {
        unsigned pl  = idx / 432u;          // local patch 0..7
        unsigned rem = idx - pl * 432u;
        unsigned i   = rem / 18u;           // patch row 0..23
        unsigned off = rem - i * 18u;       // float4 within row 0..17
        unsigned e0  = off * 4u;            // element = j*3 + c
        unsigned j   = e0 / 3u;
        unsigned c   = e0 - j * 3u;

        unsigned base = i * RSd + (pl << 4);  // + j per element, + c*CSd
        float v[4];
        #pragma unroll
        for (int k = 0; k < 4; k++) {
            v[k] = s[c * CSd + base + j];
            if (++c == 3u) { c = 0u; ++j; }
        }
        float4 o; o.x = v[0]; o.y = v[1]; o.z = v[2]; o.w = v[3];
        o4[idx] = o;
    }
}

extern "C" void kernel_launch(void* const* d_in, const int* in_sizes, int n_in,
                              void* d_out, int out_size) {
    const float* x = (const float*)d_in[0];
    float* out = (float*)d_out;
    patcher_kernel<<<4096, 256>>>(x, out, (unsigned)out_size);
}

// round 4
// speedup vs baseline: 1.5319x; 1.5319x over previous
#include <cuda_runtime.h>
#include <cstdint>

// Patcher: x (8,3,1024,1024) fp32, patch=24, stride=16, reflect pad m=4.
// out[((b*64+ph)*64+pw)*1728 + (i*24+j)*3 + c] = x[b,c,ry,rx]
//   ry=reflect(ph*16+i-4), rx=reflect(pw*16+j-4); reflect: q<0->-q, q>1023->2046-q.
//
// Block = (b, ph, pg): 8 consecutive patches (pw = 8*pg..8*pg+7).
// smem tile s[r][x][c], r=0..23, x=0..135, c=0..2  (c-FASTEST = output order).
//   Phase 1: per (r, xg): 3x LDG.128 (channel planes) -> reg transpose ->
//            3x STS.128 (conflict-free, lane word-stride 12).
//   Phase 2: output float4 idx -> smem float4 (i*102 + pl*12 + off):
//            LDS.128 + STG.128, both lane-coalesced.

static constexpr unsigned HWu = 1024u * 1024u;
static constexpr long long TOTAL_ELEMS = 56623104LL;
static constexpr unsigned ROW_F = 408u;            // 136*3 floats per smem row
static constexpr unsigned ROW_F4 = 102u;           // float4 per smem row
static constexpr unsigned SMEM_FLOATS = 24u * ROW_F;  // 9792 (39168 B)
static constexpr unsigned N_GROUPS = 24u * 34u;    // phase-1 (r, xg) groups = 816
static constexpr unsigned N_OUT4 = 8u * 432u;      // 3456 float4 per block

__device__ __forceinline__ int reflect_idx(int q) {
    q = (q < 0) ? -q : q;
    q = (q > 1023) ? (2046 - q) : q;
    return q;
}

__global__ void __launch_bounds__(256)
patcher_kernel(const float* __restrict__ x, float* __restrict__ out,
               unsigned out_size) {
    __shared__ float4 s4[SMEM_FLOATS / 4];
    float* s = reinterpret_cast<float*>(s4);

    unsigned bid = blockIdx.x;
    unsigned tid = threadIdx.x;
    unsigned pg = bid & 7u;
    unsigned ph = (bid >> 3) & 63u;
    unsigned b  = bid >> 9;

    if (bid == 0 && tid < 32u) {   // tail fill: flattened (nH,nW)=(64,64)
        unsigned idx = (unsigned)TOTAL_ELEMS + tid;
        if (idx < out_size) out[idx] = 64.0f;
    }

    // ---- Phase 1: stage + transpose ----
    const float* xb = x + (size_t)b * (3u * HWu);
    int ybase = (int)(ph << 4) - 4;
    int gx0   = (int)(pg << 7) - 4;   // tile x origin

    #pragma unroll
    for (unsigned it = 0; it < 4; ++it) {
        unsigned idx = tid + it * 256u;
        if (idx < N_GROUPS) {
            unsigned r  = idx / 34u;
            unsigned xg = idx - r * 34u;
            int y  = reflect_idx(ybase + (int)r);
            int gx = gx0 + (int)(xg << 2);

            const float* p = xb + (unsigned)y * 1024u;
            float4 a0, a1, a2;
            if (gx >= 0 && gx <= 1020) {
                a0 = *reinterpret_cast<const float4*>(p + gx);
                a1 = *reinterpret_cast<const float4*>(p + HWu + gx);
                a2 = *reinterpret_cast<const float4*>(p + 2u * HWu + gx);
            } else {
                int x0 = reflect_idx(gx), x1 = reflect_idx(gx + 1);
                int x2 = reflect_idx(gx + 2), x3 = reflect_idx(gx + 3);
                a0.x = p[x0]; a0.y = p[x1]; a0.z = p[x2]; a0.w = p[x3];
                const float* q1 = p + HWu;
                a1.x = q1[x0]; a1.y = q1[x1]; a1.z = q1[x2]; a1.w = q1[x3];
                const float* q2 = p + 2u * HWu;
                a2.x = q2[x0]; a2.y = q2[x1]; a2.z = q2[x2]; a2.w = q2[x3];
            }
            // transpose to c-fastest: x0c0,x0c1,x0c2,x1c0 | x1c1,x1c2,x2c0,x2c1 | ...
            unsigned sbase = r * ROW_F4 + xg * 3u;
            float4 t0, t1, t2;
            t0.x = a0.x; t0.y = a1.x; t0.z = a2.x; t0.w = a0.y;
            t1.x = a1.y; t1.y = a2.y; t1.z = a0.z; t1.w = a1.z;
            t2.x = a2.z; t2.y = a0.w; t2.z = a1.w; t2.w = a2.w;
            s4[sbase + 0] = t0;
            s4[sbase + 1] = t1;
            s4[sbase + 2] = t2;
        }
    }
    __syncthreads();

    // ---- Phase 2: coalesced copy out ----
    unsigned patch0 = (b << 12) + (ph << 6) + (pg << 3);
    float4* o4 = reinterpret_cast<float4*>(out) + (size_t)patch0 * 432u;

    #pragma unroll
    for (unsigned it = 0; it < 14; ++it) {
        unsigned idx = tid + it * 256u;
        if (idx < N_OUT4) {
            unsigned pl  = idx / 432u;
            unsigned rem = idx - pl * 432u;
            unsigned i   = rem / 18u;
            unsigned off = rem - i * 18u;
            o4[idx] = s4[i * ROW_F4 + pl * 12u + off];
        }
    }
}

extern "C" void kernel_launch(void* const* d_in, const int* in_sizes, int n_in,
                              void* d_out, int out_size) {
    const float* x = (const float*)d_in[0];
    float* out = (float*)d_out;
    patcher_kernel<<<4096, 256>>>(x, out, (unsigned)out_size);
}

// round 5
// speedup vs baseline: 1.8982x; 1.2391x over previous
#include <cuda_runtime.h>
#include <cstdint>

// Patcher: x (8,3,1024,1024) fp32, patch=24, stride=16, reflect pad m=4.
// out[((b*64+ph)*64+pw)*1728 + (i*24+j)*3 + c] = x[b,c,ry,rx]
//   ry=reflect(ph*16+i-4), rx=reflect(pw*16+j-4); reflect: q<0->-q, q>1023->2046-q.
//
// Block = (b, ph, pg): 4 consecutive patches (pw = 4*pg..4*pg+3).
// smem tile s[r][x][c], r=0..23, x=0..71, c=0..2 (c-fastest = output order).
//   Phase 1: per (r, xg): 3x LDG.128 (channel planes) -> reg transpose ->
//            3x STS.128 (conflict-free).
//   Phase 2: LDS.128 + STG.128, both lane-coalesced (floor wavefronts).

static constexpr unsigned HWu = 1024u * 1024u;
static constexpr long long TOTAL_ELEMS = 56623104LL;
static constexpr unsigned ROW_F4 = 54u;               // 72*3/4 float4 per smem row
static constexpr unsigned SMEM_F4 = 24u * ROW_F4;     // 1296 float4 = 20736 B
static constexpr unsigned N_GROUPS = 24u * 18u;       // (r, xg) groups = 432
static constexpr unsigned N_OUT4 = 4u * 432u;         // 1728 float4 per block

__device__ __forceinline__ int reflect_idx(int q) {
    q = (q < 0) ? -q : q;
    q = (q > 1023) ? (2046 - q) : q;
    return q;
}

__global__ void __launch_bounds__(256, 7)
patcher_kernel(const float* __restrict__ x, float* __restrict__ out,
               unsigned out_size) {
    __shared__ float4 s4[SMEM_F4];

    unsigned bid = blockIdx.x;
    unsigned tid = threadIdx.x;
    unsigned pg = bid & 15u;         // 16 groups of 4 patches
    unsigned ph = (bid >> 4) & 63u;
    unsigned b  = bid >> 10;

    if (bid == 0 && tid < 32u) {     // tail fill: flattened (nH,nW)=(64,64)
        unsigned idx = (unsigned)TOTAL_ELEMS + tid;
        if (idx < out_size) out[idx] = 64.0f;
    }

    // ---- Phase 1: stage + transpose ----
    const float* xb = x + (size_t)b * (3u * HWu);
    int ybase = (int)(ph << 4) - 4;
    int gx0   = (int)(pg << 6) - 4;   // tile x origin (pg*64 - 4)

    #pragma unroll
    for (unsigned it = 0; it < 2; ++it) {
        unsigned idx = tid + it * 256u;
        if (idx < N_GROUPS) {
            unsigned r  = idx / 18u;
            unsigned xg = idx - r * 18u;
            int y  = reflect_idx(ybase + (int)r);
            int gx = gx0 + (int)(xg << 2);

            const float* p = xb + (unsigned)y * 1024u;
            float4 a0, a1, a2;
            if (gx >= 0 && gx <= 1020) {
                a0 = *reinterpret_cast<const float4*>(p + gx);
                a1 = *reinterpret_cast<const float4*>(p + HWu + gx);
                a2 = *reinterpret_cast<const float4*>(p + 2u * HWu + gx);
            } else {
                int x0 = reflect_idx(gx), x1 = reflect_idx(gx + 1);
                int x2 = reflect_idx(gx + 2), x3 = reflect_idx(gx + 3);
                a0.x = p[x0]; a0.y = p[x1]; a0.z = p[x2]; a0.w = p[x3];
                const float* q1 = p + HWu;
                a1.x = q1[x0]; a1.y = q1[x1]; a1.z = q1[x2]; a1.w = q1[x3];
                const float* q2 = p + 2u * HWu;
                a2.x = q2[x0]; a2.y = q2[x1]; a2.z = q2[x2]; a2.w = q2[x3];
            }
            // transpose to c-fastest
            unsigned sbase = r * ROW_F4 + xg * 3u;
            float4 t0, t1, t2;
            t0.x = a0.x; t0.y = a1.x; t0.z = a2.x; t0.w = a0.y;
            t1.x = a1.y; t1.y = a2.y; t1.z = a0.z; t1.w = a1.z;
            t2.x = a2.z; t2.y = a0.w; t2.z = a1.w; t2.w = a2.w;
            s4[sbase + 0] = t0;
            s4[sbase + 1] = t1;
            s4[sbase + 2] = t2;
        }
    }
    __syncthreads();

    // ---- Phase 2: coalesced copy out ----
    unsigned patch0 = (b << 12) + (ph << 6) + (pg << 2);
    float4* o4 = reinterpret_cast<float4*>(out) + (size_t)patch0 * 432u;

    #pragma unroll
    for (unsigned it = 0; it < 7; ++it) {
        unsigned idx = tid + it * 256u;
        if (idx < N_OUT4) {
            unsigned pl  = idx / 432u;          // local patch 0..3
            unsigned rem = idx - pl * 432u;
            unsigned i   = rem / 18u;           // patch row
            unsigned off = rem - i * 18u;       // float4 in row
            o4[idx] = s4[i * ROW_F4 + pl * 12u + off];
        }
    }
}

extern "C" void kernel_launch(void* const* d_in, const int* in_sizes, int n_in,
                              void* d_out, int out_size) {
    const float* x = (const float*)d_in[0];
    float* out = (float*)d_out;
    patcher_kernel<<<8192, 256>>>(x, out, (unsigned)out_size);
}

// round 6
// speedup vs baseline: 1.9130x; 1.0078x over previous
#include <cuda_runtime.h>
#include <cstdint>

// Patcher: x (8,3,1024,1024) fp32, patch=24, stride=16, reflect pad m=4.
// out[((b*64+ph)*64+pw)*1728 + (i*24+j)*3 + c] = x[b,c,ry,rx]
//   ry=reflect(ph*16+i-4), rx=reflect(pw*16+j-4); reflect: q<0->-q, q>1023->2046-q.
//
// Block (512 thr) = (b, ph, pg): 8 consecutive patches (pw = 8*pg..8*pg+7).
// smem tile s[r][x][c], r=0..23, x=0..135, c=0..2 (c-fastest = output order).
//   Phase 1: per (r, xg): 3x LDG.128 (channel planes) -> in-lane transpose ->
//            3x STS.128 (conflict-free, lane word-stride 12).
//   Phase 2: LDS.128 + STG.128, both lane-consecutive (floor wavefronts).
// 4 CTAs/SM x 16 warps = 64 warps = full occupancy; 39.2 KB smem.

static constexpr unsigned HWu = 1024u * 1024u;
static constexpr long long TOTAL_ELEMS = 56623104LL;
static constexpr unsigned ROW_F4 = 102u;              // 136*3/4 float4 per smem row
static constexpr unsigned SMEM_F4 = 24u * ROW_F4;     // 2448 float4 = 39168 B
static constexpr unsigned N_GROUPS = 24u * 34u;       // (r, xg) groups = 816
static constexpr unsigned N_OUT4 = 8u * 432u;         // 3456 float4 per block

__device__ __forceinline__ int reflect_idx(int q) {
    q = (q < 0) ? -q : q;
    q = (q > 1023) ? (2046 - q) : q;
    return q;
}

__global__ void __launch_bounds__(512, 4)
patcher_kernel(const float* __restrict__ x, float* __restrict__ out,
               unsigned out_size) {
    __shared__ float4 s4[SMEM_F4];

    unsigned bid = blockIdx.x;
    unsigned tid = threadIdx.x;
    unsigned pg = bid & 7u;          // 8 groups of 8 patches
    unsigned ph = (bid >> 3) & 63u;
    unsigned b  = bid >> 9;

    if (bid == 0 && tid < 32u) {     // tail fill: flattened (nH,nW)=(64,64)
        unsigned idx = (unsigned)TOTAL_ELEMS + tid;
        if (idx < out_size) out[idx] = 64.0f;
    }

    // ---- Phase 1: stage + in-lane transpose ----
    const float* xb = x + (size_t)b * (3u * HWu);
    int ybase = (int)(ph << 4) - 4;
    int gx0   = (int)(pg << 7) - 4;   // tile x origin (pg*128 - 4)

    #pragma unroll
    for (unsigned it = 0; it < 2; ++it) {
        unsigned idx = tid + it * 512u;
        if (idx < N_GROUPS) {
            unsigned r  = idx / 34u;
            unsigned xg = idx - r * 34u;
            int y  = reflect_idx(ybase + (int)r);
            int gx = gx0 + (int)(xg << 2);

            const float* p = xb + (unsigned)y * 1024u;
            float4 a0, a1, a2;
            if (gx >= 0 && gx <= 1020) {
                a0 = *reinterpret_cast<const float4*>(p + gx);
                a1 = *reinterpret_cast<const float4*>(p + HWu + gx);
                a2 = *reinterpret_cast<const float4*>(p + 2u * HWu + gx);
            } else {
                int x0 = reflect_idx(gx), x1 = reflect_idx(gx + 1);
                int x2 = reflect_idx(gx + 2), x3 = reflect_idx(gx + 3);
                a0.x = p[x0]; a0.y = p[x1]; a0.z = p[x2]; a0.w = p[x3];
                const float* q1 = p + HWu;
                a1.x = q1[x0]; a1.y = q1[x1]; a1.z = q1[x2]; a1.w = q1[x3];
                const float* q2 = p + 2u * HWu;
                a2.x = q2[x0]; a2.y = q2[x1]; a2.z = q2[x2]; a2.w = q2[x3];
            }
            // transpose to c-fastest
            unsigned sbase = r * ROW_F4 + xg * 3u;
            float4 t0, t1, t2;
            t0.x = a0.x; t0.y = a1.x; t0.z = a2.x; t0.w = a0.y;
            t1.x = a1.y; t1.y = a2.y; t1.z = a0.z; t1.w = a1.z;
            t2.x = a2.z; t2.y = a0.w; t2.z = a1.w; t2.w = a2.w;
            s4[sbase + 0] = t0;
            s4[sbase + 1] = t1;
            s4[sbase + 2] = t2;
        }
    }
    __syncthreads();

    // ---- Phase 2: coalesced copy out ----
    unsigned patch0 = (b << 12) + (ph << 6) + (pg << 3);
    float4* o4 = reinterpret_cast<float4*>(out) + (size_t)patch0 * 432u;

    #pragma unroll
    for (unsigned it = 0; it < 7; ++it) {
        unsigned idx = tid + it * 512u;
        if (idx < N_OUT4) {
            unsigned pl  = idx / 432u;          // local patch 0..7
            unsigned rem = idx - pl * 432u;
            unsigned i   = rem / 18u;           // patch row
            unsigned off = rem - i * 18u;       // float4 in row
            o4[idx] = s4[i * ROW_F4 + pl * 12u + off];
        }
    }
}

extern "C" void kernel_launch(void* const* d_in, const int* in_sizes, int n_in,
                              void* d_out, int out_size) {
    const float* x = (const float*)d_in[0];
    float* out = (float*)d_out;
    patcher_kernel<<<4096, 512>>>(x, out, (unsigned)out_size);
}